// round 5
// baseline (speedup 1.0000x reference)
#include <cuda_runtime.h>

#define N_NODES     100000
#define N_EDGES     3200000
#define IN_DIM      128
#define EMB         32
#define NUM_GRAPHS  256

// ---------------- scratch (device globals; no allocations) ----------------
__device__ __align__(128) float g_xw [N_NODES * EMB];   // 12.8 MB
__device__ __align__(128) float g_agg[N_NODES * EMB];   // 12.8 MB
__device__ int   g_deg [N_NODES];
__device__ float g_dinv[N_NODES];
__device__ float g_sums[NUM_GRAPHS * EMB];
__device__ int   g_counts[NUM_GRAPHS];

// ---------------- 0) zero scratch that is accumulated into ----------------
__global__ void k_zero() {
    int i      = blockIdx.x * blockDim.x + threadIdx.x;
    int stride = gridDim.x * blockDim.x;
    for (int j = i; j < N_NODES * EMB; j += stride) g_agg[j] = 0.0f;
    for (int j = i; j < N_NODES;       j += stride) g_deg[j] = 0;
    for (int j = i; j < NUM_GRAPHS * EMB; j += stride) g_sums[j] = 0.0f;
    for (int j = i; j < NUM_GRAPHS;       j += stride) g_counts[j] = 0;
}

// ---------------- 1) xw = x @ W1  (one warp per node, lane = out col) ------
__global__ __launch_bounds__(256) void k_xw(const float* __restrict__ x,
                                            const float* __restrict__ W1) {
    __shared__ float Ws[IN_DIM * EMB];        // 16 KB, [k][c]
    for (int i = threadIdx.x; i < IN_DIM * EMB; i += blockDim.x) Ws[i] = W1[i];
    __syncthreads();

    int tid  = blockIdx.x * blockDim.x + threadIdx.x;
    int node = tid >> 5;
    int c    = tid & 31;
    if (node >= N_NODES) return;

    const float* __restrict__ xr = x + (size_t)node * IN_DIM;
    float acc = 0.0f;
#pragma unroll 16
    for (int k = 0; k < IN_DIM; k++)
        acc = fmaf(xr[k], Ws[k * EMB + c], acc);   // xr[k] is a warp broadcast
    g_xw[node * EMB + c] = acc;
}

// ---------------- 2) degree over dst ---------------------------------------
__global__ void k_deg(const int* __restrict__ dst) {
    int e = blockIdx.x * blockDim.x + threadIdx.x;
    if (e < N_EDGES) atomicAdd(&g_deg[dst[e]], 1);
}

// ---------------- 3) dinv = rsqrt(deg + 1) ---------------------------------
__global__ void k_dinv() {
    int i = blockIdx.x * blockDim.x + threadIdx.x;
    if (i < N_NODES) g_dinv[i] = rsqrtf((float)g_deg[i] + 1.0f);
}

// ---------------- 4) edge scatter: agg[dst] += xw[src] * norm --------------
__global__ __launch_bounds__(256) void k_scatter(const int* __restrict__ src,
                                                 const int* __restrict__ dst) {
    int e = blockIdx.x * blockDim.x + threadIdx.x;
    if (e >= N_EDGES) return;
    int s = src[e];
    int d = dst[e];
    float norm = g_dinv[s] * g_dinv[d];

    const float4* __restrict__ xr = (const float4*)(g_xw + (size_t)s * EMB);
    float4* ar = (float4*)(g_agg + (size_t)d * EMB);
#pragma unroll
    for (int j = 0; j < 8; j++) {
        float4 v = __ldg(&xr[j]);
        asm volatile("red.global.add.v4.f32 [%0], {%1, %2, %3, %4};"
                     :: "l"(ar + j),
                        "f"(v.x * norm), "f"(v.y * norm),
                        "f"(v.z * norm), "f"(v.w * norm)
                     : "memory");
    }
}

// ---------------- 5) h = tanh(agg + self + b1); pool per graph -------------
__global__ __launch_bounds__(256) void k_pool(const int* __restrict__ batch,
                                              const float* __restrict__ b1) {
    int tid  = blockIdx.x * blockDim.x + threadIdx.x;
    int node = tid >> 5;
    int c    = tid & 31;
    if (node >= N_NODES) return;

    float di = g_dinv[node];
    float h  = g_agg[node * EMB + c]
             + g_xw[node * EMB + c] * (di * di)
             + b1[c];
    h = tanhf(h);

    int g = batch[node];
    atomicAdd(&g_sums[g * EMB + c], h);
    if (c == 0) atomicAdd(&g_counts[g], 1);
}

// ---------------- 6) out[g] = [sums, means] @ Wout + bout ------------------
__global__ void k_out(const float* __restrict__ Wout,
                      const float* __restrict__ bout,
                      float* __restrict__ out) {
    int g = blockIdx.x;       // 256 graphs
    int c = threadIdx.x;      // 64 threads
    float cnt = fmaxf((float)g_counts[g], 1.0f);
    float s   = g_sums[g * EMB + (c & 31)];
    float v   = (c < 32 ? s : s / cnt) * Wout[c];

#pragma unroll
    for (int o = 16; o > 0; o >>= 1)
        v += __shfl_down_sync(0xffffffffu, v, o);

    __shared__ float partial[2];
    if ((c & 31) == 0) partial[c >> 5] = v;
    __syncthreads();
    if (c == 0) out[g] = partial[0] + partial[1] + bout[0];
}

// ---------------- launch ----------------------------------------------------
extern "C" void kernel_launch(void* const* d_in, const int* in_sizes, int n_in,
                              void* d_out, int out_size) {
    const float* x     = (const float*)d_in[0];
    const int*   ei    = (const int*)d_in[1];     // int64 in reference -> int32 in harness
    const int*   batch = (const int*)d_in[2];
    const float* W1    = (const float*)d_in[3];
    const float* b1    = (const float*)d_in[4];
    const float* Wout  = (const float*)d_in[5];
    const float* bout  = (const float*)d_in[6];
    float*       out   = (float*)d_out;

    const int* src = ei;            // edge_index[0]
    const int* dst = ei + N_EDGES;  // edge_index[1]

    k_zero<<<592, 256>>>();
    k_xw<<<(N_NODES * 32 + 255) / 256, 256>>>(x, W1);
    k_deg<<<(N_EDGES + 255) / 256, 256>>>(dst);
    k_dinv<<<(N_NODES + 255) / 256, 256>>>();
    k_scatter<<<(N_EDGES + 255) / 256, 256>>>(src, dst);
    k_pool<<<(N_NODES * 32 + 255) / 256, 256>>>(batch, b1);
    k_out<<<NUM_GRAPHS, 64>>>(Wout, bout, out);
}

// round 7
// speedup vs baseline: 1.5010x; 1.5010x over previous
#include <cuda_runtime.h>

#define N_NODES     100000
#define N_EDGES     3200000
#define IN_DIM      128
#define EMB         32
#define NUM_GRAPHS  256
#define NB          ((N_NODES + 255) / 256)   // 391 scan blocks

// ---------------- scratch (device globals; no allocations) ----------------
__device__ __align__(128) float g_xw  [N_NODES * EMB];   // 12.8 MB
__device__ __align__(128) int   g_csrc[N_EDGES];         // 12.8 MB: CSR src ids, bucketed by dst
__device__ int   g_deg   [N_NODES];
__device__ float g_dinv  [N_NODES];
__device__ int   g_roff  [N_NODES];   // row start
__device__ int   g_cursor[N_NODES];   // fill cursor; == row end after bucket pass
__device__ int   g_part  [NB];
__device__ int   g_partx [NB];
__device__ float g_sums  [NUM_GRAPHS * EMB];
__device__ int   g_counts[NUM_GRAPHS];

// ---------------- 0) zero accumulated scratch ------------------------------
__global__ void k_zero() {
    int i      = blockIdx.x * blockDim.x + threadIdx.x;
    int stride = gridDim.x * blockDim.x;
    for (int j = i; j < N_NODES; j += stride) g_deg[j] = 0;
    for (int j = i; j < NUM_GRAPHS * EMB; j += stride) g_sums[j] = 0.0f;
    for (int j = i; j < NUM_GRAPHS;       j += stride) g_counts[j] = 0;
}

// ---------------- 1) xw = x @ W1  (one warp per node, lane = out col) ------
__global__ __launch_bounds__(256) void k_xw(const float* __restrict__ x,
                                            const float* __restrict__ W1) {
    __shared__ float Ws[IN_DIM * EMB];        // 16 KB, [k][c]
    for (int i = threadIdx.x; i < IN_DIM * EMB; i += blockDim.x) Ws[i] = W1[i];
    __syncthreads();

    int tid  = blockIdx.x * blockDim.x + threadIdx.x;
    int node = tid >> 5;
    int c    = tid & 31;
    if (node >= N_NODES) return;

    const float* __restrict__ xr = x + (size_t)node * IN_DIM;
    float acc = 0.0f;
#pragma unroll 16
    for (int k = 0; k < IN_DIM; k++)
        acc = fmaf(xr[k], Ws[k * EMB + c], acc);   // xr[k] is a warp broadcast
    g_xw[node * EMB + c] = acc;
}

// ---------------- 2) degree over dst ---------------------------------------
__global__ void k_deg(const int* __restrict__ dst) {
    int e = blockIdx.x * blockDim.x + threadIdx.x;
    if (e < N_EDGES) atomicAdd(&g_deg[dst[e]], 1);
}

// ---------------- 3a) block partial sums of deg + dinv ---------------------
__global__ __launch_bounds__(256) void k_blocksum() {
    int t = threadIdx.x, b = blockIdx.x;
    int i = b * 256 + t;
    int d = (i < N_NODES) ? g_deg[i] : 0;
    if (i < N_NODES) g_dinv[i] = rsqrtf((float)d + 1.0f);

    __shared__ int s[256];
    s[t] = d; __syncthreads();
#pragma unroll
    for (int off = 128; off > 0; off >>= 1) {
        if (t < off) s[t] += s[t + off];
        __syncthreads();
    }
    if (t == 0) g_part[b] = s[0];
}

// ---------------- 3b) exclusive scan of the 391 block partials -------------
__global__ __launch_bounds__(512) void k_scan_part() {
    __shared__ int s[512];
    int t = threadIdx.x;
    int v = (t < NB) ? g_part[t] : 0;
    s[t] = v; __syncthreads();
#pragma unroll
    for (int off = 1; off < 512; off <<= 1) {
        int tmp = (t >= off) ? s[t - off] : 0;
        __syncthreads();
        s[t] += tmp;
        __syncthreads();
    }
    if (t < NB) g_partx[t] = s[t] - v;   // exclusive
}

// ---------------- 3c) per-node offsets (row starts) + cursors --------------
__global__ __launch_bounds__(256) void k_offsets() {
    int t = threadIdx.x, b = blockIdx.x;
    int i = b * 256 + t;
    int d = (i < N_NODES) ? g_deg[i] : 0;

    __shared__ int s[256];
    s[t] = d; __syncthreads();
#pragma unroll
    for (int off = 1; off < 256; off <<= 1) {
        int tmp = (t >= off) ? s[t - off] : 0;
        __syncthreads();
        s[t] += tmp;
        __syncthreads();
    }
    if (i < N_NODES) {
        int off0 = g_partx[b] + s[t] - d;   // exclusive within block + block base
        g_roff[i]   = off0;
        g_cursor[i] = off0;
    }
}

// ---------------- 4) bucket edges by dst (counting sort, order-free) -------
__global__ void k_bucket(const int* __restrict__ src,
                         const int* __restrict__ dst) {
    int e = blockIdx.x * blockDim.x + threadIdx.x;
    if (e >= N_EDGES) return;
    int d   = dst[e];
    int pos = atomicAdd(&g_cursor[d], 1);
    g_csrc[pos] = src[e];
}

// ---------------- 5) warp-per-node gather + tanh + graph pool --------------
__global__ __launch_bounds__(256) void k_agg(const int* __restrict__ batch,
                                             const float* __restrict__ b1) {
    int tid  = blockIdx.x * blockDim.x + threadIdx.x;
    int node = tid >> 5;
    int c    = tid & 31;
    if (node >= N_NODES) return;

    int start = g_roff[node];
    int end   = g_cursor[node];          // cursor == row end after bucket pass
    float acc = 0.0f;

    int i = start;
    // full 32-edge chunks: lane c prefetches edge i+c, broadcast via shuffle
    for (; i + 32 <= end; i += 32) {
        int   sid = g_csrc[i + c];
        float w   = g_dinv[sid];
#pragma unroll
        for (int j = 0; j < 32; j++) {
            int   sj = __shfl_sync(0xffffffffu, sid, j);
            float wj = __shfl_sync(0xffffffffu, w,   j);
            acc = fmaf(g_xw[sj * EMB + c], wj, acc);
        }
    }
    // tail
    int rem = end - i;
    if (rem > 0) {
        int   sid = 0; float w = 0.0f;
        if (c < rem) { sid = g_csrc[i + c]; w = g_dinv[sid]; }
        for (int j = 0; j < rem; j++) {
            int   sj = __shfl_sync(0xffffffffu, sid, j);
            float wj = __shfl_sync(0xffffffffu, w,   j);
            acc = fmaf(g_xw[sj * EMB + c], wj, acc);
        }
    }

    float di = g_dinv[node];
    float h  = acc * di                         // neighbor msgs: (Σ xw[s]·dinv[s]) · dinv[d]
             + g_xw[node * EMB + c] * (di * di) // self-loop
             + b1[c];
    h = tanhf(h);

    int g = batch[node];
    atomicAdd(&g_sums[g * EMB + c], h);
    if (c == 0) atomicAdd(&g_counts[g], 1);
}

// ---------------- 6) out[g] = [sums, means] @ Wout + bout ------------------
__global__ void k_out(const float* __restrict__ Wout,
                      const float* __restrict__ bout,
                      float* __restrict__ out) {
    int g = blockIdx.x;       // 256 graphs
    int c = threadIdx.x;      // 64 threads
    float cnt = fmaxf((float)g_counts[g], 1.0f);
    float s   = g_sums[g * EMB + (c & 31)];
    float v   = (c < 32 ? s : s / cnt) * Wout[c];

#pragma unroll
    for (int o = 16; o > 0; o >>= 1)
        v += __shfl_down_sync(0xffffffffu, v, o);

    __shared__ float partial[2];
    if ((c & 31) == 0) partial[c >> 5] = v;
    __syncthreads();
    if (c == 0) out[g] = partial[0] + partial[1] + bout[0];
}

// ---------------- launch ----------------------------------------------------
extern "C" void kernel_launch(void* const* d_in, const int* in_sizes, int n_in,
                              void* d_out, int out_size) {
    const float* x     = (const float*)d_in[0];
    const int*   ei    = (const int*)d_in[1];     // int64 in reference -> int32 in harness
    const int*   batch = (const int*)d_in[2];
    const float* W1    = (const float*)d_in[3];
    const float* b1    = (const float*)d_in[4];
    const float* Wout  = (const float*)d_in[5];
    const float* bout  = (const float*)d_in[6];
    float*       out   = (float*)d_out;

    const int* src = ei;            // edge_index[0]
    const int* dst = ei + N_EDGES;  // edge_index[1]

    k_zero     <<<NB, 256>>>();
    k_xw       <<<(N_NODES * 32 + 255) / 256, 256>>>(x, W1);
    k_deg      <<<(N_EDGES + 255) / 256, 256>>>(dst);
    k_blocksum <<<NB, 256>>>();
    k_scan_part<<<1, 512>>>();
    k_offsets  <<<NB, 256>>>();
    k_bucket   <<<(N_EDGES + 255) / 256, 256>>>(src, dst);
    k_agg      <<<(N_NODES * 32 + 255) / 256, 256>>>(batch, b1);
    k_out      <<<NUM_GRAPHS, 64>>>(Wout, bout, out);
}